// round 12
// baseline (speedup 1.0000x reference)
#include <cuda_runtime.h>

// Problem constants (x[8,512,8192], CHUNK=16, SE 512->64->512)
#define BB   8
#define CC   512
#define LL   8192
#define CS   16
#define NN   (LL / CS)     // 512 chunk positions
#define CH   (CC / 8)      // 64 bottleneck channels
#define NPG  8             // chunk positions per block in the gate kernel

// Static device scratch (no allocs allowed).
__device__ float g_e   [(size_t)BB * CC * NN];   // EMA output, 8 MB
__device__ float g_gate[(size_t)BB * CC * NN];   // gate, 8 MB
__device__ float g_w1t [(size_t)CC * CH];        // w1 transposed [c][o], 128 KB

// padded smem index: lane stride becomes 17 banks (conflict-free)
#define SPAD(i) ((i) + ((i) >> 4))

// ---------------------------------------------------------------------------
// Kernel 1: chunked mean pooling + causal EMA per (b, c) row.
// grid = B*C = 4096 blocks, 256 threads. Coalesced; 4-lane shfl chunk sums.
// Blocks 0..127 additionally transpose w1 (consumed only by the gate kernel,
// which launches after this kernel completes).
// ---------------------------------------------------------------------------
__global__ void __launch_bounds__(256) pool_ema_kernel(
    const float* __restrict__ x, const float* __restrict__ gamma,
    const float* __restrict__ w1)
{
    const int row = blockIdx.x;            // b*C + c
    const int c   = row & (CC - 1);
    const float g = gamma[c];
    const int t = threadIdx.x;

    // fold in the w1 transpose (32768 elems over 128 blocks)
    if (blockIdx.x < (CC * CH) / 256) {
        const int i = blockIdx.x * 256 + t;
        int o = i / CC, cw = i % CC;       // w1 [CH][CC] -> w1t [CC][CH]
        g_w1t[(size_t)cw * CH + o] = w1[i];
    }

    __shared__ float s[NN + NN / 16];      // padded chunk means

    const float4* xr = reinterpret_cast<const float4*>(x) + (size_t)row * (LL / 4);

    float4 v[8];
#pragma unroll
    for (int k = 0; k < 8; k++)
        v[k] = xr[t + k * 256];            // 8 coalesced LDG.128 in flight

#pragma unroll
    for (int k = 0; k < 8; k++) {
        float r = (v[k].x + v[k].y) + (v[k].z + v[k].w);
        r += __shfl_down_sync(0xffffffffu, r, 2, 4);
        r += __shfl_down_sync(0xffffffffu, r, 1, 4);
        if ((t & 3) == 0) {
            int ci = (t >> 2) + k * 64;    // chunk index 0..511
            s[SPAD(ci)] = r * (1.0f / 16.0f);
        }
    }
    __syncthreads();

    if (t < 32) {
        const int lane = t;
        const float omg = 1.0f - g;

        float y = 0.f;
#pragma unroll
        for (int i = 0; i < 16; i++)
            y = fmaf(g, y, omg * s[lane * 17 + i]);      // SPAD(lane*16+i)
        float Bi = y;
        float g2 = g * g, g4 = g2 * g2, g8 = g4 * g4;
        float Ai = g8 * g8;

#pragma unroll
        for (int off = 1; off < 32; off <<= 1) {
            float a_up = __shfl_up_sync(0xffffffffu, Ai, off);
            float b_up = __shfl_up_sync(0xffffffffu, Bi, off);
            if (lane >= off) {
                Bi = fmaf(Ai, b_up, Bi);
                Ai = Ai * a_up;
            }
        }
        float prefix = __shfl_up_sync(0xffffffffu, Bi, 1);
        if (lane == 0) prefix = 0.f;

        float outv[16];
        y = prefix;
#pragma unroll
        for (int i = 0; i < 16; i++) {
            y = fmaf(g, y, omg * s[lane * 17 + i]);
            outv[i] = y;
        }
        float4* er = reinterpret_cast<float4*>(g_e + (size_t)row * NN + lane * 16);
#pragma unroll
        for (int i = 0; i < 4; i++)
            er[i] = make_float4(outv[4 * i], outv[4 * i + 1], outv[4 * i + 2], outv[4 * i + 3]);
    }
}

// ---------------------------------------------------------------------------
// Kernel 2: SE bottleneck -> sigmoid gate, register-blocked.
// grid (N/NPG = 64, B = 8) = 512 blocks, 512 threads.
// GEMM1: thread = (q = tid&3 -> j-pair, o4 = (tid>>2)&15 -> 4 o-chans,
//                  cs = tid>>6 -> 64-wide c-split).
//        inner iter: 1 LDG.128(w1t) + 1 LDS.64(e) -> 8 FMA.
// GEMM2: thread = cch; w2 read in NATIVE [cch][k] layout as float4
//        (k-contiguous): 1 LDG.128 -> 32 FMA.
// ---------------------------------------------------------------------------
__global__ void __launch_bounds__(512) se_gate_kernel(
    const float* __restrict__ w2,
    const float* __restrict__ b1, const float* __restrict__ b2)
{
    const int b  = blockIdx.y;
    const int n0 = blockIdx.x * NPG;
    const int tid = threadIdx.x;

    __shared__ float es[CC][NPG];        // 16 KB e tile
    __shared__ float hpart[8][CH][9];    // 18 KB padded partials (stride 9)
    __shared__ float hs[CH][NPG];        // 2 KB final hidden

    // ---- load e tile: 1024 float4 / 512 thr = 2 each ----
    const float4* ep = reinterpret_cast<const float4*>(
        g_e + ((size_t)b * CC) * NN + n0);
#pragma unroll
    for (int i = 0; i < 2; i++) {
        int idx = tid + i * 512;                 // = c*2 + q
        int cch = idx >> 1, q = idx & 1;
        float4 v = __ldcs(ep + (size_t)cch * (NN / 4) + q);
        *reinterpret_cast<float4*>(&es[cch][q * 4]) = v;
    }
    __syncthreads();

    // ---- GEMM1 register-blocked partials ----
    {
        const int q  = tid & 3;          // j-pair: j0 = q*2
        const int o4 = (tid >> 2) & 15;  // o = o4*4 .. +3
        const int cs = tid >> 6;         // c in [cs*64, cs*64+64)
        const int j0 = q * 2;
        const int c0 = cs * 64;

        float a00 = 0.f, a01 = 0.f, a10 = 0.f, a11 = 0.f;
        float a20 = 0.f, a21 = 0.f, a30 = 0.f, a31 = 0.f;
        const float4* wp = reinterpret_cast<const float4*>(g_w1t) + o4;  // +cc*16
#pragma unroll 8
        for (int cc = c0; cc < c0 + 64; cc++) {
            float4 w = __ldg(wp + cc * (CH / 4));     // w1t[cc][o4*4..3]
            float2 e = *reinterpret_cast<const float2*>(&es[cc][j0]);
            a00 = fmaf(w.x, e.x, a00); a01 = fmaf(w.x, e.y, a01);
            a10 = fmaf(w.y, e.x, a10); a11 = fmaf(w.y, e.y, a11);
            a20 = fmaf(w.z, e.x, a20); a21 = fmaf(w.z, e.y, a21);
            a30 = fmaf(w.w, e.x, a30); a31 = fmaf(w.w, e.y, a31);
        }
        float* hp = &hpart[cs][o4 * 4][0];
        hp[0 * 9 + j0] = a00; hp[0 * 9 + j0 + 1] = a01;
        hp[1 * 9 + j0] = a10; hp[1 * 9 + j0 + 1] = a11;
        hp[2 * 9 + j0] = a20; hp[2 * 9 + j0 + 1] = a21;
        hp[3 * 9 + j0] = a30; hp[3 * 9 + j0 + 1] = a31;
    }
    __syncthreads();

    // ---- reduce 8 c-splits + bias + relu -> hs[64][8] (512 threads, 1 each) ----
    {
        const int o = tid >> 3, j = tid & 7;
        float sum = 0.f;
#pragma unroll
        for (int s2 = 0; s2 < 8; s2++)
            sum += hpart[s2][o][j];
        hs[o][j] = fmaxf(sum + b1[o], 0.f);
    }
    __syncthreads();

    // ---- GEMM2: gate = sigmoid(W2 h + b2), one channel per thread ----
    {
        const int cch = tid;               // 0..511
        float acc[NPG];
#pragma unroll
        for (int j = 0; j < NPG; j++) acc[j] = 0.f;
        const float4* wr = reinterpret_cast<const float4*>(w2 + (size_t)cch * CH);
#pragma unroll 4
        for (int k4 = 0; k4 < CH / 4; k4++) {
            float4 w = __ldg(wr + k4);
            const int k = k4 * 4;
#pragma unroll
            for (int i = 0; i < 4; i++) {
                float wk = (i == 0) ? w.x : (i == 1) ? w.y : (i == 2) ? w.z : w.w;
                float4 h0 = *reinterpret_cast<const float4*>(&hs[k + i][0]);
                float4 h1 = *reinterpret_cast<const float4*>(&hs[k + i][4]);
                acc[0] = fmaf(wk, h0.x, acc[0]); acc[1] = fmaf(wk, h0.y, acc[1]);
                acc[2] = fmaf(wk, h0.z, acc[2]); acc[3] = fmaf(wk, h0.w, acc[3]);
                acc[4] = fmaf(wk, h1.x, acc[4]); acc[5] = fmaf(wk, h1.y, acc[5]);
                acc[6] = fmaf(wk, h1.z, acc[6]); acc[7] = fmaf(wk, h1.w, acc[7]);
            }
        }
        const float bb = b2[cch];
        float4 o0, o1;
        o0.x = 1.0f / (1.0f + __expf(-(acc[0] + bb)));
        o0.y = 1.0f / (1.0f + __expf(-(acc[1] + bb)));
        o0.z = 1.0f / (1.0f + __expf(-(acc[2] + bb)));
        o0.w = 1.0f / (1.0f + __expf(-(acc[3] + bb)));
        o1.x = 1.0f / (1.0f + __expf(-(acc[4] + bb)));
        o1.y = 1.0f / (1.0f + __expf(-(acc[5] + bb)));
        o1.z = 1.0f / (1.0f + __expf(-(acc[6] + bb)));
        o1.w = 1.0f / (1.0f + __expf(-(acc[7] + bb)));
        float4* gp = reinterpret_cast<float4*>(
            g_gate + ((size_t)b * CC + cch) * NN + n0);
        gp[0] = o0;
        gp[1] = o1;
    }
}

// ---------------------------------------------------------------------------
// Kernel 3: out = gate * x, barrier-free pure stream.
// grid = 4096 blocks reversed vs pool. Gate distributed via shfl (no smem).
// x read-once (__ldcs), out streaming (__stcs).
// ---------------------------------------------------------------------------
__global__ void __launch_bounds__(256) apply_kernel(
    const float* __restrict__ x, float* __restrict__ out)
{
    const int row  = (BB * CC - 1) - blockIdx.x;      // reversed traversal
    const int t    = threadIdx.x;
    const int warp = t >> 5, lane = t & 31;

    const float* grow = g_gate + (size_t)row * NN;
    const float4* xr  = reinterpret_cast<const float4*>(x)  + (size_t)row * (LL / 4);
    float4*       orr = reinterpret_cast<float4*>(out)      + (size_t)row * (LL / 4);

    float4 v[8];
    float  gk[8];
#pragma unroll
    for (int k = 0; k < 8; k++) {
        v[k]  = __ldcs(xr + t + k * 256);
        gk[k] = grow[warp * 8 + (lane & 7) + k * 64];  // lanes 0..7 hold 8 chunks
    }
#pragma unroll
    for (int k = 0; k < 8; k++) {
        float gv = __shfl_sync(0xffffffffu, gk[k], lane >> 2);
        v[k].x *= gv; v[k].y *= gv; v[k].z *= gv; v[k].w *= gv;
        __stcs(orr + t + k * 256, v[k]);
    }
}

// ---------------------------------------------------------------------------
// kernel_launch: inputs in metadata order: x, gamma, w1, b1, w2, b2
// ---------------------------------------------------------------------------
extern "C" void kernel_launch(void* const* d_in, const int* in_sizes, int n_in,
                              void* d_out, int out_size)
{
    const float* x     = (const float*)d_in[0];
    const float* gamma = (const float*)d_in[1];
    const float* w1    = (const float*)d_in[2];
    const float* b1    = (const float*)d_in[3];
    const float* w2    = (const float*)d_in[4];
    const float* b2    = (const float*)d_in[5];
    float* out = (float*)d_out;

    pool_ema_kernel<<<BB * CC, 256>>>(x, gamma, w1);

    dim3 gridG(NN / NPG, BB);
    se_gate_kernel<<<gridG, 512>>>(w2, b1, b2);

    apply_kernel<<<BB * CC, 256>>>(x, out);
}

// round 13
// speedup vs baseline: 1.0003x; 1.0003x over previous
#include <cuda_runtime.h>

// Problem constants (x[8,512,8192], CHUNK=16, SE 512->64->512)
#define BB   8
#define CC   512
#define LL   8192
#define CS   16
#define NN   (LL / CS)     // 512 chunk positions
#define CH   (CC / 8)      // 64 bottleneck channels
#define NPG  8             // chunk positions per block in the gate kernel

// Static device scratch (no allocs allowed).
__device__ float g_e   [(size_t)BB * CC * NN];   // EMA output, 8 MB
__device__ float g_gate[(size_t)BB * CC * NN];   // gate, 8 MB
__device__ float g_w1t [(size_t)CC * CH];        // w1 transposed [c][o], 128 KB

// padded smem index: lane stride becomes 17 banks (conflict-free)
#define SPAD(i) ((i) + ((i) >> 4))

// ---------------------------------------------------------------------------
// Kernel 1: chunked mean pooling + causal EMA per (b, c) row.
// grid = B*C = 4096 blocks, 256 threads. Coalesced; 4-lane shfl chunk sums.
// Blocks 0..127 additionally transpose w1 (consumed only by the gate kernel,
// which launches after this kernel completes).
// ---------------------------------------------------------------------------
__global__ void __launch_bounds__(256) pool_ema_kernel(
    const float* __restrict__ x, const float* __restrict__ gamma,
    const float* __restrict__ w1)
{
    const int row = blockIdx.x;            // b*C + c
    const int c   = row & (CC - 1);
    const float g = gamma[c];
    const int t = threadIdx.x;

    // fold in the w1 transpose (32768 elems over 128 blocks)
    if (blockIdx.x < (CC * CH) / 256) {
        const int i = blockIdx.x * 256 + t;
        int o = i / CC, cw = i % CC;       // w1 [CH][CC] -> w1t [CC][CH]
        g_w1t[(size_t)cw * CH + o] = w1[i];
    }

    __shared__ float s[NN + NN / 16];      // padded chunk means

    const float4* xr = reinterpret_cast<const float4*>(x) + (size_t)row * (LL / 4);

    float4 v[8];
#pragma unroll
    for (int k = 0; k < 8; k++)
        v[k] = xr[t + k * 256];            // 8 coalesced LDG.128 in flight

#pragma unroll
    for (int k = 0; k < 8; k++) {
        float r = (v[k].x + v[k].y) + (v[k].z + v[k].w);
        r += __shfl_down_sync(0xffffffffu, r, 2, 4);
        r += __shfl_down_sync(0xffffffffu, r, 1, 4);
        if ((t & 3) == 0) {
            int ci = (t >> 2) + k * 64;    // chunk index 0..511
            s[SPAD(ci)] = r * (1.0f / 16.0f);
        }
    }
    __syncthreads();

    if (t < 32) {
        const int lane = t;
        const float omg = 1.0f - g;

        float y = 0.f;
#pragma unroll
        for (int i = 0; i < 16; i++)
            y = fmaf(g, y, omg * s[lane * 17 + i]);      // SPAD(lane*16+i)
        float Bi = y;
        float g2 = g * g, g4 = g2 * g2, g8 = g4 * g4;
        float Ai = g8 * g8;

#pragma unroll
        for (int off = 1; off < 32; off <<= 1) {
            float a_up = __shfl_up_sync(0xffffffffu, Ai, off);
            float b_up = __shfl_up_sync(0xffffffffu, Bi, off);
            if (lane >= off) {
                Bi = fmaf(Ai, b_up, Bi);
                Ai = Ai * a_up;
            }
        }
        float prefix = __shfl_up_sync(0xffffffffu, Bi, 1);
        if (lane == 0) prefix = 0.f;

        float outv[16];
        y = prefix;
#pragma unroll
        for (int i = 0; i < 16; i++) {
            y = fmaf(g, y, omg * s[lane * 17 + i]);
            outv[i] = y;
        }
        float4* er = reinterpret_cast<float4*>(g_e + (size_t)row * NN + lane * 16);
#pragma unroll
        for (int i = 0; i < 4; i++)
            er[i] = make_float4(outv[4 * i], outv[4 * i + 1], outv[4 * i + 2], outv[4 * i + 3]);
    }
}

// ---------------------------------------------------------------------------
// Kernel 2: SE bottleneck -> sigmoid gate, register-blocked.
// grid (N/NPG = 64, B = 8) = 512 blocks, 512 threads.
// GEMM1: thread = (q = tid&3 -> j-pair, o4 = (tid>>2)&15 -> 4 o-chans,
//                  cs = tid>>6 -> 64-wide c-split).
//        inner iter: 1 LDG.128(w1t) + 1 LDS.64(e) -> 8 FMA.
// GEMM2: thread = cch; w2 read in NATIVE [cch][k] layout as float4
//        (k-contiguous): 1 LDG.128 -> 32 FMA.
// ---------------------------------------------------------------------------
__global__ void __launch_bounds__(512) se_gate_kernel(
    const float* __restrict__ w2,
    const float* __restrict__ b1, const float* __restrict__ b2)
{
    const int b  = blockIdx.y;
    const int n0 = blockIdx.x * NPG;
    const int tid = threadIdx.x;

    __shared__ float es[CC][NPG];        // 16 KB e tile
    __shared__ float hpart[8][CH][9];    // 18 KB padded partials (stride 9)
    __shared__ float hs[CH][NPG];        // 2 KB final hidden

    // ---- load e tile: 1024 float4 / 512 thr = 2 each ----
    const float4* ep = reinterpret_cast<const float4*>(
        g_e + ((size_t)b * CC) * NN + n0);
#pragma unroll
    for (int i = 0; i < 2; i++) {
        int idx = tid + i * 512;                 // = c*2 + q
        int cch = idx >> 1, q = idx & 1;
        float4 v = __ldcs(ep + (size_t)cch * (NN / 4) + q);
        *reinterpret_cast<float4*>(&es[cch][q * 4]) = v;
    }
    __syncthreads();

    // ---- GEMM1 register-blocked partials ----
    {
        const int q  = tid & 3;          // j-pair: j0 = q*2
        const int o4 = (tid >> 2) & 15;  // o = o4*4 .. +3
        const int cs = tid >> 6;         // c in [cs*64, cs*64+64)
        const int j0 = q * 2;
        const int c0 = cs * 64;

        float a00 = 0.f, a01 = 0.f, a10 = 0.f, a11 = 0.f;
        float a20 = 0.f, a21 = 0.f, a30 = 0.f, a31 = 0.f;
        const float4* wp = reinterpret_cast<const float4*>(g_w1t) + o4;  // +cc*16
#pragma unroll 8
        for (int cc = c0; cc < c0 + 64; cc++) {
            float4 w = __ldg(wp + cc * (CH / 4));     // w1t[cc][o4*4..3]
            float2 e = *reinterpret_cast<const float2*>(&es[cc][j0]);
            a00 = fmaf(w.x, e.x, a00); a01 = fmaf(w.x, e.y, a01);
            a10 = fmaf(w.y, e.x, a10); a11 = fmaf(w.y, e.y, a11);
            a20 = fmaf(w.z, e.x, a20); a21 = fmaf(w.z, e.y, a21);
            a30 = fmaf(w.w, e.x, a30); a31 = fmaf(w.w, e.y, a31);
        }
        float* hp = &hpart[cs][o4 * 4][0];
        hp[0 * 9 + j0] = a00; hp[0 * 9 + j0 + 1] = a01;
        hp[1 * 9 + j0] = a10; hp[1 * 9 + j0 + 1] = a11;
        hp[2 * 9 + j0] = a20; hp[2 * 9 + j0 + 1] = a21;
        hp[3 * 9 + j0] = a30; hp[3 * 9 + j0 + 1] = a31;
    }
    __syncthreads();

    // ---- reduce 8 c-splits + bias + relu -> hs[64][8] (512 threads, 1 each) ----
    {
        const int o = tid >> 3, j = tid & 7;
        float sum = 0.f;
#pragma unroll
        for (int s2 = 0; s2 < 8; s2++)
            sum += hpart[s2][o][j];
        hs[o][j] = fmaxf(sum + b1[o], 0.f);
    }
    __syncthreads();

    // ---- GEMM2: gate = sigmoid(W2 h + b2), one channel per thread ----
    {
        const int cch = tid;               // 0..511
        float acc[NPG];
#pragma unroll
        for (int j = 0; j < NPG; j++) acc[j] = 0.f;
        const float4* wr = reinterpret_cast<const float4*>(w2 + (size_t)cch * CH);
#pragma unroll 4
        for (int k4 = 0; k4 < CH / 4; k4++) {
            float4 w = __ldg(wr + k4);
            const int k = k4 * 4;
#pragma unroll
            for (int i = 0; i < 4; i++) {
                float wk = (i == 0) ? w.x : (i == 1) ? w.y : (i == 2) ? w.z : w.w;
                float4 h0 = *reinterpret_cast<const float4*>(&hs[k + i][0]);
                float4 h1 = *reinterpret_cast<const float4*>(&hs[k + i][4]);
                acc[0] = fmaf(wk, h0.x, acc[0]); acc[1] = fmaf(wk, h0.y, acc[1]);
                acc[2] = fmaf(wk, h0.z, acc[2]); acc[3] = fmaf(wk, h0.w, acc[3]);
                acc[4] = fmaf(wk, h1.x, acc[4]); acc[5] = fmaf(wk, h1.y, acc[5]);
                acc[6] = fmaf(wk, h1.z, acc[6]); acc[7] = fmaf(wk, h1.w, acc[7]);
            }
        }
        const float bb = b2[cch];
        float4 o0, o1;
        o0.x = 1.0f / (1.0f + __expf(-(acc[0] + bb)));
        o0.y = 1.0f / (1.0f + __expf(-(acc[1] + bb)));
        o0.z = 1.0f / (1.0f + __expf(-(acc[2] + bb)));
        o0.w = 1.0f / (1.0f + __expf(-(acc[3] + bb)));
        o1.x = 1.0f / (1.0f + __expf(-(acc[4] + bb)));
        o1.y = 1.0f / (1.0f + __expf(-(acc[5] + bb)));
        o1.z = 1.0f / (1.0f + __expf(-(acc[6] + bb)));
        o1.w = 1.0f / (1.0f + __expf(-(acc[7] + bb)));
        float4* gp = reinterpret_cast<float4*>(
            g_gate + ((size_t)b * CC + cch) * NN + n0);
        gp[0] = o0;
        gp[1] = o1;
    }
}

// ---------------------------------------------------------------------------
// Kernel 3: out = gate * x, barrier-free pure stream.
// grid = 4096 blocks reversed vs pool. Gate distributed via shfl (no smem).
// x read-once (__ldcs), out streaming (__stcs).
// ---------------------------------------------------------------------------
__global__ void __launch_bounds__(256) apply_kernel(
    const float* __restrict__ x, float* __restrict__ out)
{
    const int row  = (BB * CC - 1) - blockIdx.x;      // reversed traversal
    const int t    = threadIdx.x;
    const int warp = t >> 5, lane = t & 31;

    const float* grow = g_gate + (size_t)row * NN;
    const float4* xr  = reinterpret_cast<const float4*>(x)  + (size_t)row * (LL / 4);
    float4*       orr = reinterpret_cast<float4*>(out)      + (size_t)row * (LL / 4);

    float4 v[8];
    float  gk[8];
#pragma unroll
    for (int k = 0; k < 8; k++) {
        v[k]  = __ldcs(xr + t + k * 256);
        gk[k] = grow[warp * 8 + (lane & 7) + k * 64];  // lanes 0..7 hold 8 chunks
    }
#pragma unroll
    for (int k = 0; k < 8; k++) {
        float gv = __shfl_sync(0xffffffffu, gk[k], lane >> 2);
        v[k].x *= gv; v[k].y *= gv; v[k].z *= gv; v[k].w *= gv;
        __stcs(orr + t + k * 256, v[k]);
    }
}

// ---------------------------------------------------------------------------
// kernel_launch: inputs in metadata order: x, gamma, w1, b1, w2, b2
// ---------------------------------------------------------------------------
extern "C" void kernel_launch(void* const* d_in, const int* in_sizes, int n_in,
                              void* d_out, int out_size)
{
    const float* x     = (const float*)d_in[0];
    const float* gamma = (const float*)d_in[1];
    const float* w1    = (const float*)d_in[2];
    const float* b1    = (const float*)d_in[3];
    const float* w2    = (const float*)d_in[4];
    const float* b2    = (const float*)d_in[5];
    float* out = (float*)d_out;

    pool_ema_kernel<<<BB * CC, 256>>>(x, gamma, w1);

    dim3 gridG(NN / NPG, BB);
    se_gate_kernel<<<gridG, 512>>>(w2, b1, b2);

    apply_kernel<<<BB * CC, 256>>>(x, out);
}